// round 5
// baseline (speedup 1.0000x reference)
#include <cuda_runtime.h>
#include <math.h>

#define N_NODES 50000
#define N_EDGES 600000
#define DIN 128
#define DOUT 256
#define EPS 1e-5f

// ---------------- scratch (no dynamic allocation allowed) ----------------
__device__ __align__(16) float g_agg[N_NODES * DIN];    // 25.6 MB
__device__ __align__(16) float g_y1[N_NODES * DOUT];    // 51.2 MB
__device__ int   g_count[N_NODES + 1];
__device__ int   g_off[N_NODES + 1];
__device__ int   g_cur[N_NODES];
__device__ int   g_csr[N_EDGES];
__device__ float g_cs[DOUT];
__device__ float g_cs2[DOUT];
__device__ float g_scale[DOUT];
__device__ float g_shift[DOUT];
__device__ int   g_is64;   // 1 if edges buffer is int64, 0 if int32

// ---------------- dtype detector ----------------
// If edges is int64 (values in [0,50000), little-endian), then viewed as int32
// every odd index is 0. If edges is int32, odd indices are random node ids.
__global__ void k_detect(const int* __restrict__ e32) {
    if (threadIdx.x == 0) {
        int is64 = 1;
        for (int i = 0; i < 256; i++) {
            if (e32[2 * i + 1] != 0) { is64 = 0; break; }
        }
        g_is64 = is64;
    }
}

__device__ __forceinline__ void load_edge(const void* edges, int e, int& src, int& dst) {
    if (g_is64) {
        const long long* p = (const long long*)edges;
        src = (int)p[e];
        dst = (int)p[N_EDGES + e];
    } else {
        const int* p = (const int*)edges;
        src = p[e];
        dst = p[N_EDGES + e];
    }
}

// ---------------- zero counters ----------------
__global__ void k_zero() {
    int t = blockIdx.x * blockDim.x + threadIdx.x;
    if (t <= N_NODES) g_count[t] = 0;
    if (t < DOUT) { g_cs[t] = 0.f; g_cs2[t] = 0.f; }
}

// ---------------- histogram of dst ----------------
__global__ void k_hist(const void* __restrict__ edges) {
    int e = blockIdx.x * blockDim.x + threadIdx.x;
    if (e >= N_EDGES) return;
    int src, dst;
    load_edge(edges, e, src, dst);
    if (dst >= 0 && dst < N_NODES) atomicAdd(&g_count[dst], 1);
}

// ---------------- exclusive scan (single block, 1024 threads) ----------------
__global__ void k_scan() {
    __shared__ int sums[1024];
    int t = threadIdx.x;
    const int CH = (N_NODES + 1023) / 1024;   // 49
    int start = t * CH;
    int end = start + CH; if (end > N_NODES) end = N_NODES;
    if (start > N_NODES) start = N_NODES;
    int s = 0;
    for (int i = start; i < end; i++) s += g_count[i];
    sums[t] = s;
    __syncthreads();
    for (int d = 1; d < 1024; d <<= 1) {
        int v = (t >= d) ? sums[t - d] : 0;
        __syncthreads();
        sums[t] += v;
        __syncthreads();
    }
    int excl = (t == 0) ? 0 : sums[t - 1];
    for (int i = start; i < end; i++) {
        int c = g_count[i];
        g_off[i] = excl;
        g_cur[i] = excl;
        excl += c;
    }
    if (t == 1023) g_off[N_NODES] = sums[1023];
}

// ---------------- scatter edge src into CSR ----------------
__global__ void k_scatter(const void* __restrict__ edges) {
    int e = blockIdx.x * blockDim.x + threadIdx.x;
    if (e >= N_EDGES) return;
    int src, dst;
    load_edge(edges, e, src, dst);
    if (dst < 0 || dst >= N_NODES || src < 0 || src >= N_NODES) return;
    int pos = atomicAdd(&g_cur[dst], 1);
    if (pos >= 0 && pos < N_EDGES) g_csr[pos] = src;
}

// ---------------- gather-sum: one warp per node ----------------
__global__ void k_gather(const float* __restrict__ x) {
    int gt = blockIdx.x * blockDim.x + threadIdx.x;
    int node = gt >> 5;
    int lane = gt & 31;
    if (node >= N_NODES) return;
    int s0 = g_off[node], s1 = g_off[node + 1];
    float4 acc = make_float4(0.f, 0.f, 0.f, 0.f);
    for (int e = s0; e < s1; e++) {
        int s = g_csr[e];
        float4 v = ((const float4*)(x + (size_t)s * DIN))[lane];
        acc.x += v.x; acc.y += v.y; acc.z += v.z; acc.w += v.w;
    }
    ((float4*)(g_agg + (size_t)node * DIN))[lane] = acc;
}

// ---------------- GEMM1: y1 = agg @ W_gcn + b_gcn, + column sum/sumsq ----------------
__global__ __launch_bounds__(256, 2) void k_gemm1(const float* __restrict__ W,
                                                  const float* __restrict__ b) {
    __shared__ float As[64][33];
    __shared__ float Ws[32][DOUT];
    int tid = threadIdx.x;
    int tc = tid & 31;
    int tr = tid >> 5;
    int block_row = blockIdx.x * 64;

    float acc[8][8];
#pragma unroll
    for (int i = 0; i < 8; i++)
#pragma unroll
        for (int j = 0; j < 8; j++) acc[i][j] = 0.f;

    for (int k0 = 0; k0 < DIN; k0 += 32) {
#pragma unroll
        for (int i = 0; i < 2; i++) {
            int idx = i * 256 + tid;
            int r = idx >> 3;
            int c4 = idx & 7;
            int grow = block_row + r;
            float4 v = make_float4(0.f, 0.f, 0.f, 0.f);
            if (grow < N_NODES)
                v = *(const float4*)&g_agg[(size_t)grow * DIN + k0 + c4 * 4];
            As[r][c4 * 4 + 0] = v.x;
            As[r][c4 * 4 + 1] = v.y;
            As[r][c4 * 4 + 2] = v.z;
            As[r][c4 * 4 + 3] = v.w;
        }
#pragma unroll
        for (int i = 0; i < 8; i++) {
            int idx = i * 256 + tid;
            int kr = idx >> 6;
            int cc = idx & 63;
            *(float4*)&Ws[kr][cc * 4] = *(const float4*)&W[(size_t)(k0 + kr) * DOUT + cc * 4];
        }
        __syncthreads();
#pragma unroll
        for (int kk = 0; kk < 32; kk++) {
            float a[8];
#pragma unroll
            for (int i = 0; i < 8; i++) a[i] = As[tr * 8 + i][kk];
            float4 b0 = *(float4*)&Ws[kk][tc * 4];
            float4 b1 = *(float4*)&Ws[kk][128 + tc * 4];
#pragma unroll
            for (int i = 0; i < 8; i++) {
                acc[i][0] += a[i] * b0.x;
                acc[i][1] += a[i] * b0.y;
                acc[i][2] += a[i] * b0.z;
                acc[i][3] += a[i] * b0.w;
                acc[i][4] += a[i] * b1.x;
                acc[i][5] += a[i] * b1.y;
                acc[i][6] += a[i] * b1.z;
                acc[i][7] += a[i] * b1.w;
            }
        }
        __syncthreads();
    }

    int c0 = tc * 4;
    int c1 = 128 + tc * 4;
    float bias[8];
#pragma unroll
    for (int j = 0; j < 4; j++) { bias[j] = b[c0 + j]; bias[4 + j] = b[c1 + j]; }

    float ps[8], ps2[8];
#pragma unroll
    for (int j = 0; j < 8; j++) { ps[j] = 0.f; ps2[j] = 0.f; }

#pragma unroll
    for (int i = 0; i < 8; i++) {
        int grow = block_row + tr * 8 + i;
        if (grow < N_NODES) {
            float v[8];
#pragma unroll
            for (int j = 0; j < 8; j++) {
                v[j] = acc[i][j] + bias[j];
                ps[j] += v[j];
                ps2[j] += v[j] * v[j];
            }
            *(float4*)&g_y1[(size_t)grow * DOUT + c0] = make_float4(v[0], v[1], v[2], v[3]);
            *(float4*)&g_y1[(size_t)grow * DOUT + c1] = make_float4(v[4], v[5], v[6], v[7]);
        }
    }

    __syncthreads();
    float (*red)[DOUT]  = (float(*)[DOUT])&Ws[0][0];
    float (*red2)[DOUT] = (float(*)[DOUT])&Ws[8][0];
#pragma unroll
    for (int j = 0; j < 4; j++) {
        red[tr][c0 + j] = ps[j];       red[tr][c1 + j] = ps[4 + j];
        red2[tr][c0 + j] = ps2[j];     red2[tr][c1 + j] = ps2[4 + j];
    }
    __syncthreads();
    {
        int c = tid;
        float s = 0.f, s2 = 0.f;
#pragma unroll
        for (int t = 0; t < 8; t++) { s += red[t][c]; s2 += red2[t][c]; }
        atomicAdd(&g_cs[c], s);
        atomicAdd(&g_cs2[c], s2);
    }
}

// ---------------- BN parameter finalize ----------------
__global__ void k_bn(const float* __restrict__ gamma, const float* __restrict__ beta) {
    int c = threadIdx.x;
    if (c >= DOUT) return;
    float invN = 1.f / (float)N_NODES;
    float mean = g_cs[c] * invN;
    float var = g_cs2[c] * invN - mean * mean;
    float sc = gamma[c] * rsqrtf(var + EPS);
    g_scale[c] = sc;
    g_shift[c] = beta[c] - mean * sc;
}

// ---------------- GEMM2: out = x @ W_sc + b_sc + elu(bn(y1)) ----------------
__global__ __launch_bounds__(256, 2) void k_gemm2(const float* __restrict__ x,
                                                  const float* __restrict__ W,
                                                  const float* __restrict__ b,
                                                  float* __restrict__ out) {
    __shared__ float As[64][33];
    __shared__ float Ws[32][DOUT];
    int tid = threadIdx.x;
    int tc = tid & 31;
    int tr = tid >> 5;
    int block_row = blockIdx.x * 64;

    float acc[8][8];
#pragma unroll
    for (int i = 0; i < 8; i++)
#pragma unroll
        for (int j = 0; j < 8; j++) acc[i][j] = 0.f;

    for (int k0 = 0; k0 < DIN; k0 += 32) {
#pragma unroll
        for (int i = 0; i < 2; i++) {
            int idx = i * 256 + tid;
            int r = idx >> 3;
            int c4 = idx & 7;
            int grow = block_row + r;
            float4 v = make_float4(0.f, 0.f, 0.f, 0.f);
            if (grow < N_NODES)
                v = *(const float4*)&x[(size_t)grow * DIN + k0 + c4 * 4];
            As[r][c4 * 4 + 0] = v.x;
            As[r][c4 * 4 + 1] = v.y;
            As[r][c4 * 4 + 2] = v.z;
            As[r][c4 * 4 + 3] = v.w;
        }
#pragma unroll
        for (int i = 0; i < 8; i++) {
            int idx = i * 256 + tid;
            int kr = idx >> 6;
            int cc = idx & 63;
            *(float4*)&Ws[kr][cc * 4] = *(const float4*)&W[(size_t)(k0 + kr) * DOUT + cc * 4];
        }
        __syncthreads();
#pragma unroll
        for (int kk = 0; kk < 32; kk++) {
            float a[8];
#pragma unroll
            for (int i = 0; i < 8; i++) a[i] = As[tr * 8 + i][kk];
            float4 b0 = *(float4*)&Ws[kk][tc * 4];
            float4 b1 = *(float4*)&Ws[kk][128 + tc * 4];
#pragma unroll
            for (int i = 0; i < 8; i++) {
                acc[i][0] += a[i] * b0.x;
                acc[i][1] += a[i] * b0.y;
                acc[i][2] += a[i] * b0.z;
                acc[i][3] += a[i] * b0.w;
                acc[i][4] += a[i] * b1.x;
                acc[i][5] += a[i] * b1.y;
                acc[i][6] += a[i] * b1.z;
                acc[i][7] += a[i] * b1.w;
            }
        }
        __syncthreads();
    }

    int c0 = tc * 4;
    int c1 = 128 + tc * 4;
    float bias[8], scl[8], shf[8];
#pragma unroll
    for (int j = 0; j < 4; j++) {
        bias[j] = b[c0 + j];       bias[4 + j] = b[c1 + j];
        scl[j]  = g_scale[c0 + j]; scl[4 + j]  = g_scale[c1 + j];
        shf[j]  = g_shift[c0 + j]; shf[4 + j]  = g_shift[c1 + j];
    }

#pragma unroll
    for (int i = 0; i < 8; i++) {
        int grow = block_row + tr * 8 + i;
        if (grow < N_NODES) {
            float4 y0 = *(const float4*)&g_y1[(size_t)grow * DOUT + c0];
            float4 y1v = *(const float4*)&g_y1[(size_t)grow * DOUT + c1];
            float yv[8] = {y0.x, y0.y, y0.z, y0.w, y1v.x, y1v.y, y1v.z, y1v.w};
            float o[8];
#pragma unroll
            for (int j = 0; j < 8; j++) {
                float v = yv[j] * scl[j] + shf[j];
                float e = (v > 0.f) ? v : expm1f(v);
                o[j] = acc[i][j] + bias[j] + e;
            }
            *(float4*)&out[(size_t)grow * DOUT + c0] = make_float4(o[0], o[1], o[2], o[3]);
            *(float4*)&out[(size_t)grow * DOUT + c1] = make_float4(o[4], o[5], o[6], o[7]);
        }
    }
}

// ---------------- launch ----------------
extern "C" void kernel_launch(void* const* d_in, const int* in_sizes, int n_in,
                              void* d_out, int out_size) {
    const float* x     = (const float*)d_in[0];
    const void*  edges = d_in[1];
    const float* W_gcn = (const float*)d_in[2];
    const float* b_gcn = (const float*)d_in[3];
    const float* gamma = (const float*)d_in[4];
    const float* beta  = (const float*)d_in[5];
    const float* W_sc  = (const float*)d_in[6];
    const float* b_sc  = (const float*)d_in[7];
    float*       out   = (float*)d_out;

    k_detect<<<1, 32>>>((const int*)edges);
    k_zero<<<(N_NODES + 1 + 255) / 256, 256>>>();
    k_hist<<<(N_EDGES + 511) / 512, 512>>>(edges);
    k_scan<<<1, 1024>>>();
    k_scatter<<<(N_EDGES + 511) / 512, 512>>>(edges);
    k_gather<<<(N_NODES * 32 + 255) / 256, 256>>>(x);
    k_gemm1<<<(N_NODES + 63) / 64, 256>>>(W_gcn, b_gcn);
    k_bn<<<1, 256>>>(gamma, beta);
    k_gemm2<<<(N_NODES + 63) / 64, 256>>>(x, W_sc, b_sc, out);
}

// round 7
// speedup vs baseline: 1.1265x; 1.1265x over previous
#include <cuda_runtime.h>
#include <cuda_bf16.h>
#include <math.h>

typedef unsigned int u32;

#define N_NODES 50000
#define N_EDGES 600000
#define DIN 128
#define DOUT 256
#define EPS 1e-5f
#define NBLK_SCAN ((N_NODES + 127) / 128)   // 391

// ---------------- scratch ----------------
__device__ __align__(16) float g_agg[N_NODES * DIN];    // 25.6 MB
__device__ __align__(16) float g_y1[N_NODES * DOUT];    // 51.2 MB
__device__ int g_count[N_NODES];
__device__ int g_off[N_NODES + 1];
__device__ int g_cur[N_NODES];
__device__ int g_csr[N_EDGES];
__device__ int g_bsum[NBLK_SCAN];
__device__ int g_boff[NBLK_SCAN];
__device__ __align__(16) float g_cs[DOUT];
__device__ __align__(16) float g_cs2[DOUT];
__device__ __align__(16) float g_scale[DOUT];
__device__ __align__(16) float g_shift[DOUT];
__device__ int g_is64;

// ---------------- dtype detector (parallel) ----------------
__global__ void k_detect(const int* __restrict__ e32) {
    int bad = (e32[2 * threadIdx.x + 1] != 0) ? 1 : 0;
    int any = __syncthreads_or(bad);
    if (threadIdx.x == 0) g_is64 = !any;
}

__device__ __forceinline__ void load_edge(const void* edges, int e, int& src, int& dst) {
    if (g_is64) {
        const long long* p = (const long long*)edges;
        src = (int)p[e];
        dst = (int)p[N_EDGES + e];
    } else {
        const int* p = (const int*)edges;
        src = p[e];
        dst = p[N_EDGES + e];
    }
}

// ---------------- zero ----------------
__global__ void k_zero() {
    int t = blockIdx.x * blockDim.x + threadIdx.x;
    if (t < N_NODES) g_count[t] = 0;
    if (t < DOUT) { g_cs[t] = 0.f; g_cs2[t] = 0.f; }
}

// ---------------- histogram of dst ----------------
__global__ void k_hist(const void* __restrict__ edges) {
    int e = blockIdx.x * blockDim.x + threadIdx.x;
    if (e >= N_EDGES) return;
    int src, dst;
    load_edge(edges, e, src, dst);
    if (dst >= 0 && dst < N_NODES) atomicAdd(&g_count[dst], 1);
}

// ---------------- parallel scan: 3 phases ----------------
__global__ void k_scan1() {     // per-block sums of 128 counts
    __shared__ int ws[4];
    int idx = blockIdx.x * 128 + threadIdx.x;
    int v = (idx < N_NODES) ? g_count[idx] : 0;
#pragma unroll
    for (int o = 16; o; o >>= 1) v += __shfl_xor_sync(0xffffffffu, v, o);
    if ((threadIdx.x & 31) == 0) ws[threadIdx.x >> 5] = v;
    __syncthreads();
    if (threadIdx.x == 0) g_bsum[blockIdx.x] = ws[0] + ws[1] + ws[2] + ws[3];
}

__global__ void k_scan2() {     // exclusive scan of 391 block sums (1 block, 512 thr)
    __shared__ int ws[16];
    int t = threadIdx.x, lane = t & 31, wid = t >> 5;
    int v = (t < NBLK_SCAN) ? g_bsum[t] : 0;
    int incl = v;
#pragma unroll
    for (int o = 1; o < 32; o <<= 1) {
        int n = __shfl_up_sync(0xffffffffu, incl, o);
        if (lane >= o) incl += n;
    }
    if (lane == 31) ws[wid] = incl;
    __syncthreads();
    if (t < 16) {
        int wv = ws[t];
#pragma unroll
        for (int o = 1; o < 16; o <<= 1) {
            int n = __shfl_up_sync(0xffffu, wv, o);
            if (t >= o) wv += n;
        }
        ws[t] = wv;   // inclusive warp prefix
    }
    __syncthreads();
    int wex = wid ? ws[wid - 1] : 0;
    int excl = wex + incl - v;
    if (t < NBLK_SCAN) g_boff[t] = excl;
    if (t == NBLK_SCAN - 1) g_off[N_NODES] = excl + v;
}

__global__ void k_scan3() {     // per-block exclusive rescan + offset
    __shared__ int ws[4];
    int tid = threadIdx.x, lane = tid & 31, wid = tid >> 5;
    int idx = blockIdx.x * 128 + tid;
    int v = (idx < N_NODES) ? g_count[idx] : 0;
    int incl = v;
#pragma unroll
    for (int o = 1; o < 32; o <<= 1) {
        int n = __shfl_up_sync(0xffffffffu, incl, o);
        if (lane >= o) incl += n;
    }
    if (lane == 31) ws[wid] = incl;
    __syncthreads();
    if (tid < 4) {
        int wv = ws[tid];
#pragma unroll
        for (int o = 1; o < 4; o <<= 1) {
            int n = __shfl_up_sync(0xfu, wv, o);
            if (tid >= o) wv += n;
        }
        ws[tid] = wv;
    }
    __syncthreads();
    int wex = wid ? ws[wid - 1] : 0;
    int excl = g_boff[blockIdx.x] + wex + incl - v;
    if (idx < N_NODES) { g_off[idx] = excl; g_cur[idx] = excl; }
}

// ---------------- scatter src into CSR ----------------
__global__ void k_scatter(const void* __restrict__ edges) {
    int e = blockIdx.x * blockDim.x + threadIdx.x;
    if (e >= N_EDGES) return;
    int src, dst;
    load_edge(edges, e, src, dst);
    if (dst < 0 || dst >= N_NODES || src < 0 || src >= N_NODES) return;
    int pos = atomicAdd(&g_cur[dst], 1);
    if (pos >= 0 && pos < N_EDGES) g_csr[pos] = src;
}

// ---------------- gather-sum: one warp per node ----------------
__global__ void k_gather(const float* __restrict__ x) {
    int gt = blockIdx.x * blockDim.x + threadIdx.x;
    int node = gt >> 5;
    int lane = gt & 31;
    if (node >= N_NODES) return;
    int s0 = g_off[node], s1 = g_off[node + 1];
    float4 acc = make_float4(0.f, 0.f, 0.f, 0.f);
    for (int e = s0; e < s1; e++) {
        int s = g_csr[e];
        float4 v = ((const float4*)(x + (size_t)s * DIN))[lane];
        acc.x += v.x; acc.y += v.y; acc.z += v.z; acc.w += v.w;
    }
    ((float4*)(g_agg + (size_t)node * DIN))[lane] = acc;
}

// ---------------- bf16 split helpers + mma ----------------
__device__ __forceinline__ void split2(float a, float b, u32& hi, u32& lo) {
    __nv_bfloat16 ha = __float2bfloat16_rn(a);
    __nv_bfloat16 hb = __float2bfloat16_rn(b);
    __nv_bfloat162 H; H.x = ha; H.y = hb;
    hi = *reinterpret_cast<u32*>(&H);
    __nv_bfloat162 L = __floats2bfloat162_rn(a - __bfloat162float(ha),
                                             b - __bfloat162float(hb));
    lo = *reinterpret_cast<u32*>(&L);
}

__device__ __forceinline__ void mma_bf16(float* c, const u32* a, u32 b0, u32 b1) {
    asm volatile(
        "mma.sync.aligned.m16n8k16.row.col.f32.bf16.bf16.f32 "
        "{%0,%1,%2,%3}, {%4,%5,%6,%7}, {%8,%9}, {%0,%1,%2,%3};\n"
        : "+f"(c[0]), "+f"(c[1]), "+f"(c[2]), "+f"(c[3])
        : "r"(a[0]), "r"(a[1]), "r"(a[2]), "r"(a[3]), "r"(b0), "r"(b1));
}

// ---------------- GEMM1: y1 = agg @ W_gcn  (+ column sum/sumsq of y1) ----------------
// BN bias algebra: (agg@W + b - mean(agg@W + b)) == (y1 - mean(y1)); b_gcn cancels.
__global__ __launch_bounds__(256, 2) void k_gemm1(const float* __restrict__ W) {
    __shared__ u32 sAhi[128][17], sAlo[128][17];
    __shared__ u32 sWhi[16][132], sWlo[16][132];
    __shared__ float s_cs[128], s_cs2[128];
    int tid = threadIdx.x;
    int lane = tid & 31, wid = tid >> 5;
    int gid = lane >> 2, tig = lane & 3;
    int warpM = wid >> 1, warpN = wid & 1;
    int rowBase = blockIdx.x * 128;
    int colBase = blockIdx.y * 128;
    if (tid < 128) { s_cs[tid] = 0.f; s_cs2[tid] = 0.f; }

    float acc[2][8][4];
#pragma unroll
    for (int mt = 0; mt < 2; mt++)
#pragma unroll
        for (int nt = 0; nt < 8; nt++)
#pragma unroll
            for (int j = 0; j < 4; j++) acc[mt][nt][j] = 0.f;

    for (int k0 = 0; k0 < DIN; k0 += 32) {
        // A tile 128x32 fp32 -> split bf16
#pragma unroll
        for (int i = 0; i < 4; i++) {
            int idx = i * 256 + tid;
            int r = idx >> 3, c4 = idx & 7;
            int grow = rowBase + r;
            float4 v = make_float4(0.f, 0.f, 0.f, 0.f);
            if (grow < N_NODES) v = *(const float4*)&g_agg[grow * DIN + k0 + 4 * c4];
            u32 h0, l0, h1, l1;
            split2(v.x, v.y, h0, l0);
            split2(v.z, v.w, h1, l1);
            sAhi[r][2 * c4] = h0; sAhi[r][2 * c4 + 1] = h1;
            sAlo[r][2 * c4] = l0; sAlo[r][2 * c4 + 1] = l1;
        }
        // W tile 32x128 fp32 -> split bf16 (packed pairs along k)
        {
            __nv_bfloat16* wh = (__nv_bfloat16*)&sWhi[0][0];
            __nv_bfloat16* wl = (__nv_bfloat16*)&sWlo[0][0];
#pragma unroll
            for (int i = 0; i < 4; i++) {
                int idx = i * 256 + tid;
                int kr = idx >> 5, c4 = idx & 31;
                float4 v = *(const float4*)&W[(k0 + kr) * DOUT + colBase + 4 * c4];
                int base = (kr >> 1) * 264 + 8 * c4 + (kr & 1);
                float vv[4] = {v.x, v.y, v.z, v.w};
#pragma unroll
                for (int j = 0; j < 4; j++) {
                    __nv_bfloat16 hi = __float2bfloat16_rn(vv[j]);
                    wh[base + 2 * j] = hi;
                    wl[base + 2 * j] = __float2bfloat16_rn(vv[j] - __bfloat162float(hi));
                }
            }
        }
        __syncthreads();
#pragma unroll
        for (int ks = 0; ks < 2; ks++) {
            u32 ahi[2][4], alo[2][4];
#pragma unroll
            for (int mt = 0; mt < 2; mt++) {
                int r0 = warpM * 32 + mt * 16 + gid;
                int kb = ks * 8 + tig;
                ahi[mt][0] = sAhi[r0][kb];     ahi[mt][1] = sAhi[r0 + 8][kb];
                ahi[mt][2] = sAhi[r0][kb + 4]; ahi[mt][3] = sAhi[r0 + 8][kb + 4];
                alo[mt][0] = sAlo[r0][kb];     alo[mt][1] = sAlo[r0 + 8][kb];
                alo[mt][2] = sAlo[r0][kb + 4]; alo[mt][3] = sAlo[r0 + 8][kb + 4];
            }
#pragma unroll
            for (int nt = 0; nt < 8; nt++) {
                int c = warpN * 64 + nt * 8 + gid;
                u32 bh0 = sWhi[ks * 8 + tig][c], bh1 = sWhi[ks * 8 + 4 + tig][c];
                u32 bl0 = sWlo[ks * 8 + tig][c], bl1 = sWlo[ks * 8 + 4 + tig][c];
#pragma unroll
                for (int mt = 0; mt < 2; mt++) {
                    mma_bf16(acc[mt][nt], ahi[mt], bh0, bh1);
                    mma_bf16(acc[mt][nt], ahi[mt], bl0, bl1);
                    mma_bf16(acc[mt][nt], alo[mt], bh0, bh1);
                }
            }
        }
        __syncthreads();
    }

    // epilogue: store y1, reduce column sums/sumsq
#pragma unroll
    for (int nt = 0; nt < 8; nt++) {
        int c = colBase + warpN * 64 + nt * 8 + 2 * tig;
        float s0 = 0.f, s1 = 0.f, q0 = 0.f, q1 = 0.f;
#pragma unroll
        for (int mt = 0; mt < 2; mt++) {
            int r0 = rowBase + warpM * 32 + mt * 16 + gid;
            float v0 = acc[mt][nt][0], v1 = acc[mt][nt][1];
            float v2 = acc[mt][nt][2], v3 = acc[mt][nt][3];
            if (r0 < N_NODES)     *(float2*)&g_y1[r0 * DOUT + c]       = make_float2(v0, v1);
            if (r0 + 8 < N_NODES) *(float2*)&g_y1[(r0 + 8) * DOUT + c] = make_float2(v2, v3);
            s0 += v0 + v2; s1 += v1 + v3;
            q0 += v0 * v0 + v2 * v2; q1 += v1 * v1 + v3 * v3;
        }
#pragma unroll
        for (int off = 16; off >= 4; off >>= 1) {
            s0 += __shfl_xor_sync(0xffffffffu, s0, off);
            s1 += __shfl_xor_sync(0xffffffffu, s1, off);
            q0 += __shfl_xor_sync(0xffffffffu, q0, off);
            q1 += __shfl_xor_sync(0xffffffffu, q1, off);
        }
        if (gid == 0) {
            int lc = warpN * 64 + nt * 8 + 2 * tig;
            atomicAdd(&s_cs[lc], s0);      atomicAdd(&s_cs[lc + 1], s1);
            atomicAdd(&s_cs2[lc], q0);     atomicAdd(&s_cs2[lc + 1], q1);
        }
    }
    __syncthreads();
    if (tid < 128) {
        atomicAdd(&g_cs[colBase + tid], s_cs[tid]);
        atomicAdd(&g_cs2[colBase + tid], s_cs2[tid]);
    }
}

// ---------------- BN finalize ----------------
__global__ void k_bn(const float* __restrict__ gamma, const float* __restrict__ beta) {
    int c = threadIdx.x;
    if (c >= DOUT) return;
    float invN = 1.f / (float)N_NODES;
    float mean = g_cs[c] * invN;
    float var = g_cs2[c] * invN - mean * mean;
    float sc = gamma[c] * rsqrtf(var + EPS);
    g_scale[c] = sc;
    g_shift[c] = beta[c] - mean * sc;
}

// ---------------- GEMM2: out = x @ W_sc + b_sc + elu(y1*scale + shift) ----------------
__global__ __launch_bounds__(256, 2) void k_gemm2(const float* __restrict__ A,
                                                  const float* __restrict__ W,
                                                  const float* __restrict__ bsc,
                                                  float* __restrict__ out) {
    __shared__ u32 sAhi[128][17], sAlo[128][17];
    __shared__ u32 sWhi[16][132], sWlo[16][132];
    int tid = threadIdx.x;
    int lane = tid & 31, wid = tid >> 5;
    int gid = lane >> 2, tig = lane & 3;
    int warpM = wid >> 1, warpN = wid & 1;
    int rowBase = blockIdx.x * 128;
    int colBase = blockIdx.y * 128;

    float acc[2][8][4];
#pragma unroll
    for (int mt = 0; mt < 2; mt++)
#pragma unroll
        for (int nt = 0; nt < 8; nt++)
#pragma unroll
            for (int j = 0; j < 4; j++) acc[mt][nt][j] = 0.f;

    for (int k0 = 0; k0 < DIN; k0 += 32) {
#pragma unroll
        for (int i = 0; i < 4; i++) {
            int idx = i * 256 + tid;
            int r = idx >> 3, c4 = idx & 7;
            int grow = rowBase + r;
            float4 v = make_float4(0.f, 0.f, 0.f, 0.f);
            if (grow < N_NODES) v = *(const float4*)&A[grow * DIN + k0 + 4 * c4];
            u32 h0, l0, h1, l1;
            split2(v.x, v.y, h0, l0);
            split2(v.z, v.w, h1, l1);
            sAhi[r][2 * c4] = h0; sAhi[r][2 * c4 + 1] = h1;
            sAlo[r][2 * c4] = l0; sAlo[r][2 * c4 + 1] = l1;
        }
        {
            __nv_bfloat16* wh = (__nv_bfloat16*)&sWhi[0][0];
            __nv_bfloat16* wl = (__nv_bfloat16*)&sWlo[0][0];
#pragma unroll
            for (int i = 0; i < 4; i++) {
                int idx = i * 256 + tid;
                int kr = idx >> 5, c4 = idx & 31;
                float4 v = *(const float4*)&W[(k0 + kr) * DOUT + colBase + 4 * c4];
                int base = (kr >> 1) * 264 + 8 * c4 + (kr & 1);
                float vv[4] = {v.x, v.y, v.z, v.w};
#pragma unroll
                for (int j = 0; j < 4; j++) {
                    __nv_bfloat16 hi = __float2bfloat16_rn(vv[j]);
                    wh[base + 2 * j] = hi;
                    wl[base + 2 * j] = __float2bfloat16_rn(vv[j] - __bfloat162float(hi));
                }
            }
        }
        __syncthreads();
#pragma unroll
        for (int ks = 0; ks < 2; ks++) {
            u32 ahi[2][4], alo[2][4];
#pragma unroll
            for (int mt = 0; mt < 2; mt++) {
                int r0 = warpM * 32 + mt * 16 + gid;
                int kb = ks * 8 + tig;
                ahi[mt][0] = sAhi[r0][kb];     ahi[mt][1] = sAhi[r0 + 8][kb];
                ahi[mt][2] = sAhi[r0][kb + 4]; ahi[mt][3] = sAhi[r0 + 8][kb + 4];
                alo[mt][0] = sAlo[r0][kb];     alo[mt][1] = sAlo[r0 + 8][kb];
                alo[mt][2] = sAlo[r0][kb + 4]; alo[mt][3] = sAlo[r0 + 8][kb + 4];
            }
#pragma unroll
            for (int nt = 0; nt < 8; nt++) {
                int c = warpN * 64 + nt * 8 + gid;
                u32 bh0 = sWhi[ks * 8 + tig][c], bh1 = sWhi[ks * 8 + 4 + tig][c];
                u32 bl0 = sWlo[ks * 8 + tig][c], bl1 = sWlo[ks * 8 + 4 + tig][c];
#pragma unroll
                for (int mt = 0; mt < 2; mt++) {
                    mma_bf16(acc[mt][nt], ahi[mt], bh0, bh1);
                    mma_bf16(acc[mt][nt], ahi[mt], bl0, bl1);
                    mma_bf16(acc[mt][nt], alo[mt], bh0, bh1);
                }
            }
        }
        __syncthreads();
    }

    // epilogue: residual + BN-ELU branch
#pragma unroll
    for (int nt = 0; nt < 8; nt++) {
        int c = colBase + warpN * 64 + nt * 8 + 2 * tig;
        float2 scl = *(const float2*)&g_scale[c];
        float2 shf = *(const float2*)&g_shift[c];
        float2 bb  = *(const float2*)&bsc[c];
#pragma unroll
        for (int mt = 0; mt < 2; mt++) {
            int r0 = rowBase + warpM * 32 + mt * 16 + gid;
#pragma unroll
            for (int half = 0; half < 2; half++) {
                int r = r0 + half * 8;
                if (r < N_NODES) {
                    float2 y = *(const float2*)&g_y1[r * DOUT + c];
                    float a0 = acc[mt][nt][half * 2 + 0];
                    float a1 = acc[mt][nt][half * 2 + 1];
                    float u0 = y.x * scl.x + shf.x;
                    float u1 = y.y * scl.y + shf.y;
                    float e0 = (u0 > 0.f) ? u0 : expm1f(u0);
                    float e1 = (u1 > 0.f) ? u1 : expm1f(u1);
                    *(float2*)&out[r * DOUT + c] = make_float2(a0 + bb.x + e0, a1 + bb.y + e1);
                }
            }
        }
    }
}

// ---------------- launch ----------------
extern "C" void kernel_launch(void* const* d_in, const int* in_sizes, int n_in,
                              void* d_out, int out_size) {
    const float* x     = (const float*)d_in[0];
    const void*  edges = d_in[1];
    const float* W_gcn = (const float*)d_in[2];
    // d_in[3] = b_gcn: cancels exactly inside BN (out - mean(out)); unused.
    const float* gamma = (const float*)d_in[4];
    const float* beta  = (const float*)d_in[5];
    const float* W_sc  = (const float*)d_in[6];
    const float* b_sc  = (const float*)d_in[7];
    float*       out   = (float*)d_out;

    k_detect<<<1, 256>>>((const int*)edges);
    k_zero<<<(N_NODES + 255) / 256, 256>>>();
    k_hist<<<(N_EDGES + 511) / 512, 512>>>(edges);
    k_scan1<<<NBLK_SCAN, 128>>>();
    k_scan2<<<1, 512>>>();
    k_scan3<<<NBLK_SCAN, 128>>>();
    k_scatter<<<(N_EDGES + 511) / 512, 512>>>(edges);
    k_gather<<<(N_NODES * 32 + 255) / 256, 256>>>(x);
    k_gemm1<<<dim3((N_NODES + 127) / 128, 2), 256>>>(W_gcn);
    k_bn<<<1, 256>>>(gamma, beta);
    k_gemm2<<<dim3((N_NODES + 127) / 128, 2), 256>>>(x, W_sc, b_sc, out);
}

// round 10
// speedup vs baseline: 1.6796x; 1.4910x over previous
#include <cuda_runtime.h>
#include <cuda_bf16.h>
#include <math.h>

typedef unsigned int u32;

#define N_NODES 50000
#define N_EDGES 600000
#define DIN 128
#define DOUT 256
#define EPS 1e-5f
#define NBLK_SCAN ((N_NODES + 127) / 128)   // 391

// ---------------- scratch ----------------
__device__ __align__(16) u32 g_aggh[N_NODES * 64];   // agg split-hi, bf16x2 k-pairs
__device__ __align__(16) u32 g_aggl[N_NODES * 64];   // agg split-lo
__device__ __align__(16) u32 g_xh[N_NODES * 64];     // x split-hi
__device__ __align__(16) u32 g_xl[N_NODES * 64];     // x split-lo
__device__ __align__(16) u32 g_W1h[64 * DOUT], g_W1l[64 * DOUT];  // W_gcn split
__device__ __align__(16) u32 g_W2h[64 * DOUT], g_W2l[64 * DOUT];  // W_sc split
__device__ __align__(16) float g_y1[N_NODES * DOUT]; // 51.2 MB
__device__ int g_count[N_NODES];
__device__ int g_off[N_NODES + 1];
__device__ int g_cur[N_NODES];
__device__ int g_csr[N_EDGES];
__device__ int g_bsum[NBLK_SCAN];
__device__ int g_boff[NBLK_SCAN];
__device__ __align__(16) float g_cs[DOUT];
__device__ __align__(16) float g_cs2[DOUT];
__device__ __align__(16) float g_scale[DOUT];
__device__ __align__(16) float g_shift[DOUT];
__device__ int g_is64;

// ---------------- dtype detector ----------------
__global__ void k_detect(const int* __restrict__ e32) {
    int bad = (e32[2 * threadIdx.x + 1] != 0) ? 1 : 0;
    int any = __syncthreads_or(bad);
    if (threadIdx.x == 0) g_is64 = !any;
}

__device__ __forceinline__ void load_edge(const void* edges, int e, int& src, int& dst) {
    if (g_is64) {
        const long long* p = (const long long*)edges;
        src = (int)p[e];
        dst = (int)p[N_EDGES + e];
    } else {
        const int* p = (const int*)edges;
        src = p[e];
        dst = p[N_EDGES + e];
    }
}

// ---------------- zero ----------------
__global__ void k_zero() {
    int t = blockIdx.x * blockDim.x + threadIdx.x;
    if (t < N_NODES) g_count[t] = 0;
    if (t < DOUT) { g_cs[t] = 0.f; g_cs2[t] = 0.f; }
}

// ---------------- histogram ----------------
__global__ void k_hist(const void* __restrict__ edges) {
    int e = blockIdx.x * blockDim.x + threadIdx.x;
    if (e >= N_EDGES) return;
    int src, dst;
    load_edge(edges, e, src, dst);
    if (dst >= 0 && dst < N_NODES) atomicAdd(&g_count[dst], 1);
}

// ---------------- parallel scan ----------------
__global__ void k_scan1() {
    __shared__ int ws[4];
    int idx = blockIdx.x * 128 + threadIdx.x;
    int v = (idx < N_NODES) ? g_count[idx] : 0;
#pragma unroll
    for (int o = 16; o; o >>= 1) v += __shfl_xor_sync(0xffffffffu, v, o);
    if ((threadIdx.x & 31) == 0) ws[threadIdx.x >> 5] = v;
    __syncthreads();
    if (threadIdx.x == 0) g_bsum[blockIdx.x] = ws[0] + ws[1] + ws[2] + ws[3];
}

__global__ void k_scan2() {
    __shared__ int ws[16];
    int t = threadIdx.x, lane = t & 31, wid = t >> 5;
    int v = (t < NBLK_SCAN) ? g_bsum[t] : 0;
    int incl = v;
#pragma unroll
    for (int o = 1; o < 32; o <<= 1) {
        int n = __shfl_up_sync(0xffffffffu, incl, o);
        if (lane >= o) incl += n;
    }
    if (lane == 31) ws[wid] = incl;
    __syncthreads();
    if (t < 16) {
        int wv = ws[t];
#pragma unroll
        for (int o = 1; o < 16; o <<= 1) {
            int n = __shfl_up_sync(0xffffu, wv, o);
            if (t >= o) wv += n;
        }
        ws[t] = wv;
    }
    __syncthreads();
    int wex = wid ? ws[wid - 1] : 0;
    int excl = wex + incl - v;
    if (t < NBLK_SCAN) g_boff[t] = excl;
    if (t == NBLK_SCAN - 1) g_off[N_NODES] = excl + v;
}

__global__ void k_scan3() {
    __shared__ int ws[4];
    int tid = threadIdx.x, lane = tid & 31, wid = tid >> 5;
    int idx = blockIdx.x * 128 + tid;
    int v = (idx < N_NODES) ? g_count[idx] : 0;
    int incl = v;
#pragma unroll
    for (int o = 1; o < 32; o <<= 1) {
        int n = __shfl_up_sync(0xffffffffu, incl, o);
        if (lane >= o) incl += n;
    }
    if (lane == 31) ws[wid] = incl;
    __syncthreads();
    if (tid < 4) {
        int wv = ws[tid];
#pragma unroll
        for (int o = 1; o < 4; o <<= 1) {
            int n = __shfl_up_sync(0xfu, wv, o);
            if (tid >= o) wv += n;
        }
        ws[tid] = wv;
    }
    __syncthreads();
    int wex = wid ? ws[wid - 1] : 0;
    int excl = g_boff[blockIdx.x] + wex + incl - v;
    if (idx < N_NODES) { g_off[idx] = excl; g_cur[idx] = excl; }
}

// ---------------- scatter ----------------
__global__ void k_scatter(const void* __restrict__ edges) {
    int e = blockIdx.x * blockDim.x + threadIdx.x;
    if (e >= N_EDGES) return;
    int src, dst;
    load_edge(edges, e, src, dst);
    if (dst < 0 || dst >= N_NODES || src < 0 || src >= N_NODES) return;
    int pos = atomicAdd(&g_cur[dst], 1);
    if (pos >= 0 && pos < N_EDGES) g_csr[pos] = src;
}

// ---------------- split helper ----------------
__device__ __forceinline__ void split2(float a, float b, u32& hi, u32& lo) {
    __nv_bfloat16 ha = __float2bfloat16_rn(a);
    __nv_bfloat16 hb = __float2bfloat16_rn(b);
    __nv_bfloat162 H; H.x = ha; H.y = hb;
    hi = *reinterpret_cast<u32*>(&H);
    __nv_bfloat162 L = __floats2bfloat162_rn(a - __bfloat162float(ha),
                                             b - __bfloat162float(hb));
    lo = *reinterpret_cast<u32*>(&L);
}

// ---------------- gather-sum -> split bf16 output ----------------
__global__ void k_gather(const float* __restrict__ x) {
    int gt = blockIdx.x * blockDim.x + threadIdx.x;
    int node = gt >> 5;
    int lane = gt & 31;
    if (node >= N_NODES) return;
    int s0 = g_off[node], s1 = g_off[node + 1];
    float4 acc = make_float4(0.f, 0.f, 0.f, 0.f);
    for (int e = s0; e < s1; e++) {
        int s = g_csr[e];
        float4 v = ((const float4*)(x + (size_t)s * DIN))[lane];
        acc.x += v.x; acc.y += v.y; acc.z += v.z; acc.w += v.w;
    }
    u32 h0, l0, h1, l1;
    split2(acc.x, acc.y, h0, l0);
    split2(acc.z, acc.w, h1, l1);
    int base = node * 64 + 2 * lane;
    *(uint2*)&g_aggh[base] = make_uint2(h0, h1);
    *(uint2*)&g_aggl[base] = make_uint2(l0, l1);
}

// ---------------- pre-split x ----------------
__global__ void k_convx(const float* __restrict__ x) {
    int t = blockIdx.x * blockDim.x + threadIdx.x;      // one per 2 k-pairs
    if (t >= N_NODES * 32) return;
    float4 v = *(const float4*)&x[t * 4];
    u32 h0, l0, h1, l1;
    split2(v.x, v.y, h0, l0);
    split2(v.z, v.w, h1, l1);
    *(uint2*)&g_xh[t * 2] = make_uint2(h0, h1);
    *(uint2*)&g_xl[t * 2] = make_uint2(l0, l1);
}

// ---------------- pre-split both weight matrices ----------------
__global__ void k_convw(const float* __restrict__ W1, const float* __restrict__ W2) {
    int t = blockIdx.x * blockDim.x + threadIdx.x;      // 64*256 elements
    if (t >= 64 * DOUT) return;
    int kp = t >> 8, c = t & 255;
    float a1 = W1[(2 * kp) * DOUT + c], b1 = W1[(2 * kp + 1) * DOUT + c];
    float a2 = W2[(2 * kp) * DOUT + c], b2 = W2[(2 * kp + 1) * DOUT + c];
    u32 h, l;
    split2(a1, b1, h, l); g_W1h[t] = h; g_W1l[t] = l;
    split2(a2, b2, h, l); g_W2h[t] = h; g_W2l[t] = l;
}

// ---------------- mma ----------------
__device__ __forceinline__ void mma_bf16(float* c, const u32* a, u32 b0, u32 b1) {
    asm volatile(
        "mma.sync.aligned.m16n8k16.row.col.f32.bf16.bf16.f32 "
        "{%0,%1,%2,%3}, {%4,%5,%6,%7}, {%8,%9}, {%0,%1,%2,%3};\n"
        : "+f"(c[0]), "+f"(c[1]), "+f"(c[2]), "+f"(c[3])
        : "r"(a[0]), "r"(a[1]), "r"(a[2]), "r"(a[3]), "r"(b0), "r"(b1));
}

// A smem: [128][20] u32 (pad 20 -> uint4-aligned rows AND conflict-free frag loads)
// W smem: [16][132] u32
#define ASTR 20
#define WSTR 132

// shared mainloop: fills + 48 MMAs per k-chunk
#define GEMM_MAINLOOP(AH, AL, WH, WL)                                              \
    for (int k0 = 0; k0 < DIN; k0 += 32) {                                         \
        int pb = k0 >> 1;                                                          \
        _Pragma("unroll")                                                          \
        for (int i = 0; i < 2; i++) {                                              \
            int idx = i * 256 + tid;                                               \
            int r = idx >> 2, j4 = (idx & 3) * 4;                                  \
            int grow = rowBase + r;                                                \
            uint4 vh = make_uint4(0u,0u,0u,0u), vl = make_uint4(0u,0u,0u,0u);      \
            if (grow < N_NODES) {                                                  \
                vh = *(const uint4*)&AH[grow * 64 + pb + j4];                      \
                vl = *(const uint4*)&AL[grow * 64 + pb + j4];                      \
            }                                                                      \
            *(uint4*)&sAh[r * ASTR + j4] = vh;                                     \
            *(uint4*)&sAl[r * ASTR + j4] = vl;                                     \
        }                                                                          \
        _Pragma("unroll")                                                          \
        for (int i = 0; i < 2; i++) {                                              \
            int idx = i * 256 + tid;                                               \
            int kr = idx >> 5, c4 = (idx & 31) * 4;                                \
            uint4 vh = *(const uint4*)&WH[(pb + kr) * DOUT + colBase + c4];        \
            uint4 vl = *(const uint4*)&WL[(pb + kr) * DOUT + colBase + c4];        \
            *(uint4*)&sWh[kr * WSTR + c4] = vh;                                    \
            *(uint4*)&sWl[kr * WSTR + c4] = vl;                                    \
        }                                                                          \
        __syncthreads();                                                           \
        _Pragma("unroll")                                                          \
        for (int ks = 0; ks < 2; ks++) {                                           \
            u32 ahi[2][4], alo[2][4];                                              \
            _Pragma("unroll")                                                      \
            for (int mt = 0; mt < 2; mt++) {                                       \
                int r0 = warpM * 32 + mt * 16 + gid;                               \
                int kb = ks * 8 + tig;                                             \
                ahi[mt][0] = sAh[r0 * ASTR + kb];                                  \
                ahi[mt][1] = sAh[(r0 + 8) * ASTR + kb];                            \
                ahi[mt][2] = sAh[r0 * ASTR + kb + 4];                              \
                ahi[mt][3] = sAh[(r0 + 8) * ASTR + kb + 4];                        \
                alo[mt][0] = sAl[r0 * ASTR + kb];                                  \
                alo[mt][1] = sAl[(r0 + 8) * ASTR + kb];                            \
                alo[mt][2] = sAl[r0 * ASTR + kb + 4];                              \
                alo[mt][3] = sAl[(r0 + 8) * ASTR + kb + 4];                        \
            }                                                                      \
            _Pragma("unroll")                                                      \
            for (int nt = 0; nt < 8; nt++) {                                       \
                int c = warpN * 64 + nt * 8 + gid;                                 \
                u32 bh0 = sWh[(ks * 8 + tig) * WSTR + c];                          \
                u32 bh1 = sWh[(ks * 8 + 4 + tig) * WSTR + c];                      \
                u32 bl0 = sWl[(ks * 8 + tig) * WSTR + c];                          \
                u32 bl1 = sWl[(ks * 8 + 4 + tig) * WSTR + c];                      \
                _Pragma("unroll")                                                  \
                for (int mt = 0; mt < 2; mt++) {                                   \
                    mma_bf16(acc[mt][nt], ahi[mt], bh0, bh1);                      \
                    mma_bf16(acc[mt][nt], ahi[mt], bl0, bl1);                      \
                    mma_bf16(acc[mt][nt], alo[mt], bh0, bh1);                      \
                }                                                                  \
            }                                                                      \
        }                                                                          \
        __syncthreads();                                                           \
    }

// ---------------- GEMM1: y1 = agg @ W_gcn (+ col sum/sumsq); b_gcn cancels in BN --------
__global__ __launch_bounds__(256, 2) void k_gemm1() {
    __shared__ u32 sAh[128 * ASTR], sAl[128 * ASTR];
    __shared__ u32 sWh[16 * WSTR], sWl[16 * WSTR];
    __shared__ float s_cs[128], s_cs2[128];
    int tid = threadIdx.x;
    int lane = tid & 31, wid = tid >> 5;
    int gid = lane >> 2, tig = lane & 3;
    int warpM = wid >> 1, warpN = wid & 1;
    int rowBase = blockIdx.x * 128;
    int colBase = blockIdx.y * 128;
    if (tid < 128) { s_cs[tid] = 0.f; s_cs2[tid] = 0.f; }

    float acc[2][8][4];
#pragma unroll
    for (int mt = 0; mt < 2; mt++)
#pragma unroll
        for (int nt = 0; nt < 8; nt++)
#pragma unroll
            for (int j = 0; j < 4; j++) acc[mt][nt][j] = 0.f;

    GEMM_MAINLOOP(g_aggh, g_aggl, g_W1h, g_W1l)

#pragma unroll
    for (int nt = 0; nt < 8; nt++) {
        int c = colBase + warpN * 64 + nt * 8 + 2 * tig;
        float s0 = 0.f, s1 = 0.f, q0 = 0.f, q1 = 0.f;
#pragma unroll
        for (int mt = 0; mt < 2; mt++) {
            int r0 = rowBase + warpM * 32 + mt * 16 + gid;
            float v0 = acc[mt][nt][0], v1 = acc[mt][nt][1];
            float v2 = acc[mt][nt][2], v3 = acc[mt][nt][3];
            if (r0 < N_NODES)     *(float2*)&g_y1[r0 * DOUT + c]       = make_float2(v0, v1);
            if (r0 + 8 < N_NODES) *(float2*)&g_y1[(r0 + 8) * DOUT + c] = make_float2(v2, v3);
            s0 += v0 + v2; s1 += v1 + v3;
            q0 += v0 * v0 + v2 * v2; q1 += v1 * v1 + v3 * v3;
        }
#pragma unroll
        for (int off = 16; off >= 4; off >>= 1) {
            s0 += __shfl_xor_sync(0xffffffffu, s0, off);
            s1 += __shfl_xor_sync(0xffffffffu, s1, off);
            q0 += __shfl_xor_sync(0xffffffffu, q0, off);
            q1 += __shfl_xor_sync(0xffffffffu, q1, off);
        }
        if (gid == 0) {
            int lc = warpN * 64 + nt * 8 + 2 * tig;
            atomicAdd(&s_cs[lc], s0);      atomicAdd(&s_cs[lc + 1], s1);
            atomicAdd(&s_cs2[lc], q0);     atomicAdd(&s_cs2[lc + 1], q1);
        }
    }
    __syncthreads();
    if (tid < 128) {
        atomicAdd(&g_cs[colBase + tid], s_cs[tid]);
        atomicAdd(&g_cs2[colBase + tid], s_cs2[tid]);
    }
}

// ---------------- BN finalize ----------------
__global__ void k_bn(const float* __restrict__ gamma, const float* __restrict__ beta) {
    int c = threadIdx.x;
    if (c >= DOUT) return;
    float invN = 1.f / (float)N_NODES;
    float mean = g_cs[c] * invN;
    float var = g_cs2[c] * invN - mean * mean;
    float sc = gamma[c] * rsqrtf(var + EPS);
    g_scale[c] = sc;
    g_shift[c] = beta[c] - mean * sc;
}

// ---------------- GEMM2: out = x @ W_sc + b_sc + elu(y1*scale + shift) ----------------
__global__ __launch_bounds__(256, 2) void k_gemm2(const float* __restrict__ bsc,
                                                  float* __restrict__ out) {
    __shared__ u32 sAh[128 * ASTR], sAl[128 * ASTR];
    __shared__ u32 sWh[16 * WSTR], sWl[16 * WSTR];
    int tid = threadIdx.x;
    int lane = tid & 31, wid = tid >> 5;
    int gid = lane >> 2, tig = lane & 3;
    int warpM = wid >> 1, warpN = wid & 1;
    int rowBase = blockIdx.x * 128;
    int colBase = blockIdx.y * 128;

    float acc[2][8][4];
#pragma unroll
    for (int mt = 0; mt < 2; mt++)
#pragma unroll
        for (int nt = 0; nt < 8; nt++)
#pragma unroll
            for (int j = 0; j < 4; j++) acc[mt][nt][j] = 0.f;

    GEMM_MAINLOOP(g_xh, g_xl, g_W2h, g_W2l)

#pragma unroll
    for (int nt = 0; nt < 8; nt++) {
        int c = colBase + warpN * 64 + nt * 8 + 2 * tig;
        float2 scl = *(const float2*)&g_scale[c];
        float2 shf = *(const float2*)&g_shift[c];
        float2 bb  = *(const float2*)&bsc[c];
#pragma unroll
        for (int mt = 0; mt < 2; mt++) {
            int r0 = rowBase + warpM * 32 + mt * 16 + gid;
#pragma unroll
            for (int half = 0; half < 2; half++) {
                int r = r0 + half * 8;
                if (r < N_NODES) {
                    float2 y = *(const float2*)&g_y1[r * DOUT + c];
                    float a0 = acc[mt][nt][half * 2 + 0];
                    float a1 = acc[mt][nt][half * 2 + 1];
                    float u0 = y.x * scl.x + shf.x;
                    float u1 = y.y * scl.y + shf.y;
                    float e0 = (u0 > 0.f) ? u0 : expm1f(u0);
                    float e1 = (u1 > 0.f) ? u1 : expm1f(u1);
                    *(float2*)&out[r * DOUT + c] = make_float2(a0 + bb.x + e0, a1 + bb.y + e1);
                }
            }
        }
    }
}

// ---------------- launch ----------------
extern "C" void kernel_launch(void* const* d_in, const int* in_sizes, int n_in,
                              void* d_out, int out_size) {
    const float* x     = (const float*)d_in[0];
    const void*  edges = d_in[1];
    const float* W_gcn = (const float*)d_in[2];
    // d_in[3] = b_gcn: cancels exactly inside BN; unused.
    const float* gamma = (const float*)d_in[4];
    const float* beta  = (const float*)d_in[5];
    const float* W_sc  = (const float*)d_in[6];
    const float* b_sc  = (const float*)d_in[7];
    float*       out   = (float*)d_out;

    k_detect<<<1, 256>>>((const int*)edges);
    k_zero<<<(N_NODES + 255) / 256, 256>>>();
    k_hist<<<(N_EDGES + 511) / 512, 512>>>(edges);
    k_scan1<<<NBLK_SCAN, 128>>>();
    k_scan2<<<1, 512>>>();
    k_scan3<<<NBLK_SCAN, 128>>>();
    k_scatter<<<(N_EDGES + 511) / 512, 512>>>(edges);
    k_convx<<<(N_NODES * 32 + 255) / 256, 256>>>(x);
    k_convw<<<(64 * DOUT + 255) / 256, 256>>>(W_gcn, W_sc);
    k_gather<<<(N_NODES * 32 + 255) / 256, 256>>>(x);
    k_gemm1<<<dim3((N_NODES + 127) / 128, 2), 256>>>();
    k_bn<<<1, 256>>>(gamma, beta);
    k_gemm2<<<dim3((N_NODES + 127) / 128, 2), 256>>>(b_sc, out);
}